// round 17
// baseline (speedup 1.0000x reference)
#include <cuda_runtime.h>
#include <cuda_bf16.h>
#include <cstdint>

#define DEVINL __device__ __forceinline__

// ---------------- problem dims ----------------
#define MTOK 16384   // B*S = 8*2048
#define DIN  4096
#define DOUT 4096

// ---------------- scratch (device globals; no allocs allowed) ----------------
__device__ int8_t g_xq[(size_t)MTOK * DIN];          // 64 MB int8 activations
__device__ int8_t g_wq[(size_t)DOUT * DIN];          // 16 MB int8 weights, row-major
__device__ uint32_t g_wqt[(size_t)(DIN / 4) * DOUT]; // 16 MB weights, k-major u32 [DIN/4][DOUT]
__device__ float g_inv_scale[MTOK];                  // per-token 1/(scale_x*scale_w)

// ---------------- PTX helpers ----------------
DEVINL uint32_t smem_u32(const void* p) {
    uint32_t a;
    asm("{ .reg .u64 t; cvta.to.shared.u64 t, %1; cvt.u32.u64 %0, t; }" : "=r"(a) : "l"(p));
    return a;
}
DEVINL void cp_async16(uint32_t dst, const void* src) {
    asm volatile("cp.async.cg.shared.global [%0], [%1], 16;" :: "r"(dst), "l"(src) : "memory");
}
DEVINL void cp_commit() { asm volatile("cp.async.commit_group;" ::: "memory"); }
template <int N>
DEVINL void cp_wait() { asm volatile("cp.async.wait_group %0;" :: "n"(N) : "memory"); }
DEVINL void ldsm_x4(uint32_t& r0, uint32_t& r1, uint32_t& r2, uint32_t& r3, uint32_t addr) {
    asm volatile("ldmatrix.sync.aligned.m8n8.x4.shared.b16 {%0,%1,%2,%3}, [%4];"
                 : "=r"(r0), "=r"(r1), "=r"(r2), "=r"(r3) : "r"(addr));
}
DEVINL void imma16832(int* d, const uint32_t* a, const uint32_t* b) {
    asm volatile(
        "mma.sync.aligned.m16n8k32.row.col.s32.s8.s8.s32 "
        "{%0,%1,%2,%3}, {%4,%5,%6,%7}, {%8,%9}, {%0,%1,%2,%3};"
        : "+r"(d[0]), "+r"(d[1]), "+r"(d[2]), "+r"(d[3])
        : "r"(a[0]), "r"(a[1]), "r"(a[2]), "r"(a[3]), "r"(b[0]), "r"(b[1]));
}

// ============================================================================
// Kernel 1: fused RMSNorm+quant (blocks 0..MTOK-1) and weight convert+transpose
// (blocks MTOK..MTOK+1023): g_wq (row-major) + g_wqt (k-major) via smem tiles.
// ============================================================================
#define WTBLOCKS 1024    // 64x64-word tiles over the 4096 x 1024-word matrix
__global__ __launch_bounds__(256) void quant_fused_kernel(
    const float* __restrict__ x, const float* __restrict__ w,
    const float* __restrict__ gamma, const float* __restrict__ scale_w)
{
    __shared__ uint32_t tbuf[64][65];
    const int tid = threadIdx.x;

    if (blockIdx.x >= MTOK) {
        const int wb = blockIdx.x - MTOK;
        const int n0 = (wb >> 4) * 64;
        const int kw0 = (wb & 15) * 64;
        const float4* wr = reinterpret_cast<const float4*>(w);
        uint32_t* wq32 = reinterpret_cast<uint32_t*>(g_wq);
#pragma unroll
        for (int i = 0; i < 16; ++i) {
            int c = tid + i * 256;
            int row = c >> 6;
            int col = c & 63;
            size_t g = (size_t)(n0 + row) * (DIN / 4) + kw0 + col;
            float4 v = wr[g];
            int q0 = (int)v.x, q1 = (int)v.y, q2 = (int)v.z, q3 = (int)v.w;
            uint32_t p = (uint32_t)(q0 & 0xFF) | ((uint32_t)(q1 & 0xFF) << 8) |
                         ((uint32_t)(q2 & 0xFF) << 16) | ((uint32_t)(q3 & 0xFF) << 24);
            wq32[g] = p;
            tbuf[row][col] = p;
        }
        __syncthreads();
#pragma unroll
        for (int i = 0; i < 4; ++i) {
            int c = tid + i * 256;
            int kwr = c >> 4;
            int nc = c & 15;
            uint4 o;
            o.x = tbuf[nc * 4 + 0][kwr];
            o.y = tbuf[nc * 4 + 1][kwr];
            o.z = tbuf[nc * 4 + 2][kwr];
            o.w = tbuf[nc * 4 + 3][kwr];
            *reinterpret_cast<uint4*>(g_wqt + (size_t)(kw0 + kwr) * DOUT + n0 + nc * 4) = o;
        }
        return;
    }

    const int token = blockIdx.x;
    const float4* xr = reinterpret_cast<const float4*>(x + (size_t)token * DIN);
    const float4* gr = reinterpret_cast<const float4*>(gamma);

    float4 v[4];
    float ss = 0.f;
#pragma unroll
    for (int i = 0; i < 4; ++i) {
        v[i] = xr[i * 256 + tid];
        ss += v[i].x * v[i].x + v[i].y * v[i].y + v[i].z * v[i].z + v[i].w * v[i].w;
    }
    __shared__ float red[8];
    __shared__ float redm[8];
#pragma unroll
    for (int o = 16; o; o >>= 1) ss += __shfl_xor_sync(~0u, ss, o);
    if ((tid & 31) == 0) red[tid >> 5] = ss;
    __syncthreads();
    float tot = 0.f;
#pragma unroll
    for (int i = 0; i < 8; ++i) tot += red[i];
    const float varg = tot * (1.0f / DIN) + 1e-5f;
    float rstd = rsqrtf(varg);
    rstd = rstd * (1.5f - 0.5f * varg * rstd * rstd);

    float xn[16];
    float amax = 0.f;
#pragma unroll
    for (int i = 0; i < 4; ++i) {
        float4 g = gr[i * 256 + tid];
        xn[i * 4 + 0] = v[i].x * rstd * g.x;
        xn[i * 4 + 1] = v[i].y * rstd * g.y;
        xn[i * 4 + 2] = v[i].z * rstd * g.z;
        xn[i * 4 + 3] = v[i].w * rstd * g.w;
#pragma unroll
        for (int j = 0; j < 4; ++j) amax = fmaxf(amax, fabsf(xn[i * 4 + j]));
    }
#pragma unroll
    for (int o = 16; o; o >>= 1) amax = fmaxf(amax, __shfl_xor_sync(~0u, amax, o));
    if ((tid & 31) == 0) redm[tid >> 5] = amax;
    __syncthreads();
    float am = 0.f;
#pragma unroll
    for (int i = 0; i < 8; ++i) am = fmaxf(am, redm[i]);
    const float sx = 127.0f / fmaxf(am, 1e-5f);

    uint32_t* oq = reinterpret_cast<uint32_t*>(g_xq + (size_t)token * DIN);
#pragma unroll
    for (int i = 0; i < 4; ++i) {
        int q[4];
#pragma unroll
        for (int j = 0; j < 4; ++j) {
            float r = rintf(xn[i * 4 + j] * sx);
            r = fminf(fmaxf(r, -128.f), 127.f);
            q[j] = (int)r;
        }
        uint32_t p = (uint32_t)(q[0] & 0xFF) | ((uint32_t)(q[1] & 0xFF) << 8) |
                     ((uint32_t)(q[2] & 0xFF) << 16) | ((uint32_t)(q[3] & 0xFF) << 24);
        oq[i * 256 + tid] = p;
    }
    if (tid == 0) g_inv_scale[token] = 1.0f / (sx * scale_w[0]);
}

// ============================================================================
// Kernel 2: warp-fused HYBRID GEMM, rate-matched split. Tile 128x128.
//   warps 0-2 (96 thr):  IMMA (tensor pipe)  -> cols [0,48)
//   warps 3-7 (160 thr): dp4a (fma/IDP pipe) -> cols [48,128)
// ============================================================================
#define BM 128
#define BN 128
#define BK 128
#define STAGES 3
#define ITERS (DIN / BK)                 // 32
#define ICOLS 48
#define DCOLS 80
#define SA_BYTES (BM * 128)              // 16 KB A tile (swizzled row-major)
#define SBI_BYTES (ICOLS * 128)          // 6 KB imma B rows 0..47 (swizzled)
#define SBD_PAD 84                       // u32 row stride (80 data + 4 pad)
#define SBD_BYTES (32 * SBD_PAD * 4)     // 10752 B dp4a B k-major [32 kw][80 n]
#define STAGE_BYTES (SA_BYTES + SBI_BYTES + SBD_BYTES)   // 33280
#define SMEM_DYN_TOTAL (STAGES * STAGE_BYTES)            // 99840

__global__ __launch_bounds__(256, 2)
void gemm_hybrid_kernel(const float* __restrict__ bias, float* __restrict__ out)
{
    extern __shared__ __align__(1024) char smem[];
    const uint32_t sbase = smem_u32(smem);
    const int tid = threadIdx.x;
    const int wid = tid >> 5, lane = tid & 31;
    const int tile_n = blockIdx.x;
    const int tile_m = blockIdx.y;

    const int8_t* Ag = g_xq + (size_t)tile_m * BM * DIN;
    const int8_t* Bg = g_wq + (size_t)tile_n * BN * DIN;              // rows 0..47 used
    const uint32_t* Wt = g_wqt + tile_n * BN + ICOLS;                 // cols 48..127

    // loader: 256 threads cover A (1024x16B) + Bi (384x16B) + Bd (640x16B)
    auto load_stage = [&](int it, int s) {
        const uint32_t sa = sbase + s * STAGE_BYTES;
        const uint32_t sbi = sa + SA_BYTES;
        const uint32_t sbd = sbi + SBI_BYTES;
        const int8_t* ap = Ag + (size_t)it * BK;
        const int8_t* bp = Bg + (size_t)it * BK;
        const uint32_t* wp = Wt + (size_t)(it * 32) * DOUT;
#pragma unroll
        for (int i = 0; i < 4; ++i) {         // A: 1024 x 16B
            int c = tid + i * 256;
            int r = c >> 3, j = c & 7;
            uint32_t off = (uint32_t)(r * 128) + (uint32_t)((j * 16) ^ ((r & 7) << 4));
            cp_async16(sa + off, ap + (size_t)r * DIN + j * 16);
        }
#pragma unroll
        for (int i = 0; i < 2; ++i) {         // Bi: 48 rows = 384 x 16B
            int c = tid + i * 256;
            if (c < 384) {
                int r = c >> 3, j = c & 7;
                uint32_t off = (uint32_t)(r * 128) + (uint32_t)((j * 16) ^ ((r & 7) << 4));
                cp_async16(sbi + off, bp + (size_t)r * DIN + j * 16);
            }
        }
#pragma unroll
        for (int i = 0; i < 3; ++i) {         // Bd: 32 kw x 80 u32 = 640 x 16B
            int c = tid + i * 256;
            if (c < 640) {
                int kw = c / 20, cg = c % 20;
                cp_async16(sbd + (uint32_t)(kw * (SBD_PAD * 4) + cg * 16),
                           wp + (size_t)kw * DOUT + cg * 4);
            }
        }
    };

    if (wid < 3) {
        // ==================== IMMA path: cols [0,48) ====================
        // Each warp: all 128 rows x 16 cols (8 m-tiles x 2 n-tiles).
        const int am = lane >> 3, ar = lane & 7;
        const uint32_t a_rowoff = (uint32_t)((((am & 1) << 3) + ar) * 128);
        const uint32_t a_bbase = (uint32_t)((am >> 1) * 16);
        const uint32_t a_xor = (uint32_t)(ar << 4);
        const uint32_t b_rowoff = (uint32_t)((wid * 16 + ((am >> 1) * 8) + ar) * 128);
        const uint32_t b_bbase = (uint32_t)((am & 1) * 16);
        const uint32_t b_xor = (uint32_t)(ar << 4);

        int accv[8][2][4];
#pragma unroll
        for (int mt = 0; mt < 8; ++mt)
#pragma unroll
            for (int nt = 0; nt < 2; ++nt)
#pragma unroll
                for (int q = 0; q < 4; ++q) accv[mt][nt][q] = 0;

        load_stage(0, 0); cp_commit();
        load_stage(1, 1); cp_commit();

        for (int it = 0; it < ITERS; ++it) {
            cp_wait<1>();
            __syncthreads();
            if (it + 2 < ITERS) load_stage(it + 2, (it + 2) % STAGES);
            cp_commit();

            const uint32_t sa = sbase + (it % STAGES) * STAGE_BYTES;
            const uint32_t sbi = sa + SA_BYTES;
#pragma unroll
            for (int ks = 0; ks < 4; ++ks) {
                uint32_t b[2][2];
                {
                    uint32_t addr = sbi + b_rowoff +
                                    (((uint32_t)(ks * 32) + b_bbase) ^ b_xor);
                    ldsm_x4(b[0][0], b[0][1], b[1][0], b[1][1], addr);
                }
                uint32_t a[8][4];
#pragma unroll
                for (int mt = 0; mt < 8; ++mt) {
                    uint32_t addr = sa + a_rowoff + mt * (16 * 128) +
                                    (((uint32_t)(ks * 32) + a_bbase) ^ a_xor);
                    ldsm_x4(a[mt][0], a[mt][1], a[mt][2], a[mt][3], addr);
                }
#pragma unroll
                for (int mt = 0; mt < 8; ++mt)
#pragma unroll
                    for (int nt = 0; nt < 2; ++nt)
                        imma16832(accv[mt][nt], a[mt], b[nt]);
            }
        }

        const int row0 = tile_m * BM + (lane >> 2);
        const int col0 = tile_n * BN + wid * 16 + (lane & 3) * 2;
#pragma unroll
        for (int mt = 0; mt < 8; ++mt) {
            const int rlo = row0 + mt * 16;
            const float inv_lo = g_inv_scale[rlo];
            const float inv_hi = g_inv_scale[rlo + 8];
#pragma unroll
            for (int nt = 0; nt < 2; ++nt) {
                const int c = col0 + nt * 8;
                const float b0 = __ldg(bias + c);
                const float b1 = __ldg(bias + c + 1);
                float2 lo, hi;
                lo.x = (float)accv[mt][nt][0] * inv_lo + b0;
                lo.y = (float)accv[mt][nt][1] * inv_lo + b1;
                hi.x = (float)accv[mt][nt][2] * inv_hi + b0;
                hi.y = (float)accv[mt][nt][3] * inv_hi + b1;
                *reinterpret_cast<float2*>(out + (size_t)rlo * DOUT + c) = lo;
                *reinterpret_cast<float2*>(out + (size_t)(rlo + 8) * DOUT + c) = hi;
            }
        }
    } else {
        // ==================== dp4a path: cols [48,128) ====================
        const int dtid = tid - 96;      // 0..159
        const int ry = dtid / 20;       // 0..7  -> rows ry*16 .. +16
        const int cx = dtid % 20;       // 0..19 -> cols 48 + cx*4 .. +4

        int acc[16][4];
#pragma unroll
        for (int i = 0; i < 16; ++i)
#pragma unroll
            for (int j = 0; j < 4; ++j) acc[i][j] = 0;

        load_stage(0, 0); cp_commit();
        load_stage(1, 1); cp_commit();

        for (int it = 0; it < ITERS; ++it) {
            cp_wait<1>();
            __syncthreads();
            if (it + 2 < ITERS) load_stage(it + 2, (it + 2) % STAGES);
            cp_commit();

            const uint32_t soff = (it % STAGES) * STAGE_BYTES;
            const char* sa = smem + soff;
            const char* sbd = smem + soff + SA_BYTES + SBI_BYTES;
#pragma unroll 1
            for (int g = 0; g < 8; ++g) {
                uint4 b0 = *reinterpret_cast<const uint4*>(sbd + (4 * g + 0) * (SBD_PAD * 4) + cx * 16);
                uint4 b1 = *reinterpret_cast<const uint4*>(sbd + (4 * g + 1) * (SBD_PAD * 4) + cx * 16);
                uint4 b2 = *reinterpret_cast<const uint4*>(sbd + (4 * g + 2) * (SBD_PAD * 4) + cx * 16);
                uint4 b3 = *reinterpret_cast<const uint4*>(sbd + (4 * g + 3) * (SBD_PAD * 4) + cx * 16);
#pragma unroll
                for (int h = 0; h < 2; ++h) {
                    uint4 a[8];
#pragma unroll
                    for (int i = 0; i < 8; ++i) {
                        const int r = ry * 16 + h * 8 + i;
                        a[i] = *reinterpret_cast<const uint4*>(
                            sa + r * 128 + (((uint32_t)g ^ (uint32_t)i) << 4));
                    }
#pragma unroll
                    for (int i = 0; i < 8; ++i) {
                        const int rr = h * 8 + i;
                        acc[rr][0] = __dp4a((int)a[i].x, (int)b0.x, acc[rr][0]);
                        acc[rr][0] = __dp4a((int)a[i].y, (int)b1.x, acc[rr][0]);
                        acc[rr][0] = __dp4a((int)a[i].z, (int)b2.x, acc[rr][0]);
                        acc[rr][0] = __dp4a((int)a[i].w, (int)b3.x, acc[rr][0]);
                        acc[rr][1] = __dp4a((int)a[i].x, (int)b0.y, acc[rr][1]);
                        acc[rr][1] = __dp4a((int)a[i].y, (int)b1.y, acc[rr][1]);
                        acc[rr][1] = __dp4a((int)a[i].z, (int)b2.y, acc[rr][1]);
                        acc[rr][1] = __dp4a((int)a[i].w, (int)b3.y, acc[rr][1]);
                        acc[rr][2] = __dp4a((int)a[i].x, (int)b0.z, acc[rr][2]);
                        acc[rr][2] = __dp4a((int)a[i].y, (int)b1.z, acc[rr][2]);
                        acc[rr][2] = __dp4a((int)a[i].z, (int)b2.z, acc[rr][2]);
                        acc[rr][2] = __dp4a((int)a[i].w, (int)b3.z, acc[rr][2]);
                        acc[rr][3] = __dp4a((int)a[i].x, (int)b0.w, acc[rr][3]);
                        acc[rr][3] = __dp4a((int)a[i].y, (int)b1.w, acc[rr][3]);
                        acc[rr][3] = __dp4a((int)a[i].z, (int)b2.w, acc[rr][3]);
                        acc[rr][3] = __dp4a((int)a[i].w, (int)b3.w, acc[rr][3]);
                    }
                }
            }
        }

        const int col0 = tile_n * BN + ICOLS + cx * 4;
        float4 bv;
        bv.x = __ldg(bias + col0 + 0);
        bv.y = __ldg(bias + col0 + 1);
        bv.z = __ldg(bias + col0 + 2);
        bv.w = __ldg(bias + col0 + 3);
#pragma unroll
        for (int i = 0; i < 16; ++i) {
            const int row = tile_m * BM + ry * 16 + i;
            const float inv = g_inv_scale[row];
            float4 r4;
            r4.x = (float)acc[i][0] * inv + bv.x;
            r4.y = (float)acc[i][1] * inv + bv.y;
            r4.z = (float)acc[i][2] * inv + bv.z;
            r4.w = (float)acc[i][3] * inv + bv.w;
            *reinterpret_cast<float4*>(out + (size_t)row * DOUT + col0) = r4;
        }
    }
}

// ============================================================================
// launch
// ============================================================================
extern "C" void kernel_launch(void* const* d_in, const int* in_sizes, int n_in,
                              void* d_out, int out_size) {
    (void)in_sizes; (void)n_in; (void)out_size;
    const float* x       = (const float*)d_in[0];
    const float* w       = (const float*)d_in[1];
    const float* scale_w = (const float*)d_in[2];
    const float* gamma   = (const float*)d_in[3];
    const float* bias    = (const float*)d_in[4];
    float* out = (float*)d_out;

    cudaFuncSetAttribute(gemm_hybrid_kernel, cudaFuncAttributeMaxDynamicSharedMemorySize,
                         SMEM_DYN_TOTAL);

    quant_fused_kernel<<<MTOK + WTBLOCKS, 256>>>(x, w, gamma, scale_w);
    gemm_hybrid_kernel<<<dim3(DOUT / BN, MTOK / BM), 256, SMEM_DYN_TOTAL>>>(bias, out);
}